// round 5
// baseline (speedup 1.0000x reference)
#include <cuda_runtime.h>
#include <cuda_bf16.h>
#include <stdint.h>

// GCN mean aggregation:
//   out[i, :] = mean over {nodes[i]} ∪ neigh_idx[i, 0..K-1] of features[idx, :]
// features [V=100000, D=128] f32, nodes [B] int{32|64}, neigh [B,32] int{32|64}.
//
// Half-warp per node: 16 lanes x 32B (LDG.256 v8.b32) = one 512B feature row
// per load instruction -> half the LDG/shfl instructions per byte vs LDG.128.
//  - feature loads: ld.global.nc.L2::evict_last.v8.b32 (table reused ~16.5x)
//  - index loads / output stores: streaming (.cs)
//  - 64 indices per warp fetched as one coalesced v2 load per lane.

static constexpr int KN = 32;
static constexpr float INV_CNT = 1.0f / 33.0f;

__device__ int g_idx_is64;

__global__ void detect_idx_dtype(const int* __restrict__ p) {
    // little-endian int64 values < 2^31 have all odd 32-bit words zero
    int all0 = 1;
#pragma unroll
    for (int i = 0; i < 64; i++) all0 &= (p[2 * i + 1] == 0);
    g_idx_is64 = all0;
}

struct F8 { float v[8]; };

// 256-bit keep-resident load: one half-warp (16 lanes x 32B) covers a 512B row.
__device__ __forceinline__ F8 ldg256_keep(const float* p) {
    F8 r;
    asm volatile(
        "ld.global.nc.L2::evict_last.v8.b32 {%0,%1,%2,%3,%4,%5,%6,%7}, [%8];"
        : "=f"(r.v[0]), "=f"(r.v[1]), "=f"(r.v[2]), "=f"(r.v[3]),
          "=f"(r.v[4]), "=f"(r.v[5]), "=f"(r.v[6]), "=f"(r.v[7])
        : "l"(p));
    return r;
}

__device__ __forceinline__ void stg_stream4(float* p, float a, float b, float c, float d) {
    asm volatile("st.global.cs.v4.f32 [%0], {%1,%2,%3,%4};"
                 :: "l"(p), "f"(a), "f"(b), "f"(c), "f"(d) : "memory");
}

__device__ __forceinline__ longlong2 ldg_cs64x2(const long long* p) {
    longlong2 v;
    asm volatile("ld.global.cs.v2.s64 {%0,%1}, [%2];"
                 : "=l"(v.x), "=l"(v.y) : "l"(p));
    return v;
}

__device__ __forceinline__ int2 ldg_cs32x2(const int* p) {
    int2 v;
    asm volatile("ld.global.cs.v2.s32 {%0,%1}, [%2];"
                 : "=r"(v.x), "=r"(v.y) : "l"(p));
    return v;
}

__device__ __forceinline__ long long ldg_cs64(const long long* p) {
    long long v;
    asm volatile("ld.global.cs.s64 %0, [%1];" : "=l"(v) : "l"(p));
    return v;
}

__device__ __forceinline__ int ldg_cs32(const int* p) {
    int v;
    asm volatile("ld.global.cs.s32 %0, [%1];" : "=r"(v) : "l"(p));
    return v;
}

__global__ __launch_bounds__(256) void gcn_agg_kernel(
    const float* __restrict__ feat,
    const void*  __restrict__ nodes,
    const void*  __restrict__ neigh,
    float*       __restrict__ out,
    int B)
{
    const int warp = (blockIdx.x * blockDim.x + threadIdx.x) >> 5;
    const int lane = threadIdx.x & 31;
    const int half = lane >> 4;       // 0 or 1: which node of the pair
    const int hl   = lane & 15;       // lane within half-warp
    const int node = warp * 2 + half;
    if (node >= B) return;

    // 64 neighbor indices per warp (2 nodes x 32), coalesced: lane l holds
    // combined indices {2l, 2l+1}. Node A's 32 live in lanes 0-15, B's in 16-31.
    int i0, i1, self_idx;
    if (g_idx_is64) {
        longlong2 p = ldg_cs64x2((const long long*)neigh + (long long)warp * 2 * KN + 2 * lane);
        i0 = (int)p.x; i1 = (int)p.y;
        self_idx = (int)ldg_cs64((const long long*)nodes + node);
    } else {
        int2 p = ldg_cs32x2((const int*)neigh + (long long)warp * 2 * KN + 2 * lane);
        i0 = p.x; i1 = p.y;
        self_idx = ldg_cs32((const int*)nodes + node);
    }

    const int col = hl * 8;           // this lane's 8-float slice of the row

    // self row
    F8 s = ldg256_keep(feat + (long long)self_idx * 128 + col);
    float acc[8];
#pragma unroll
    for (int e = 0; e < 8; e++) acc[e] = s.v[e];

    // 16 shuffle pairs -> 32 neighbor rows per node
#pragma unroll
    for (int j2 = 0; j2 < 16; j2++) {
        const int src = half * 16 + j2;   // per-half source lane
        const int ia = __shfl_sync(0xffffffffu, i0, src);
        const int ib = __shfl_sync(0xffffffffu, i1, src);
        const F8 va = ldg256_keep(feat + (long long)ia * 128 + col);
        const F8 vb = ldg256_keep(feat + (long long)ib * 128 + col);
#pragma unroll
        for (int e = 0; e < 8; e++) acc[e] += va.v[e] + vb.v[e];
    }

#pragma unroll
    for (int e = 0; e < 8; e++) acc[e] *= INV_CNT;

    float* op = out + (long long)node * 128 + col;
    stg_stream4(op + 0, acc[0], acc[1], acc[2], acc[3]);
    stg_stream4(op + 4, acc[4], acc[5], acc[6], acc[7]);
}

extern "C" void kernel_launch(void* const* d_in, const int* in_sizes, int n_in,
                              void* d_out, int out_size) {
    const float* feat  = (const float*)d_in[0];
    const void*  nodes = d_in[1];
    const void*  neigh = d_in[2];
    float*       out   = (float*)d_out;

    const int B = in_sizes[1];  // 50000

    detect_idx_dtype<<<1, 1>>>((const int*)nodes);

    const int threads = 256;                       // 8 warps = 16 nodes/block
    const int warps   = (B + 1) / 2;
    const int blocks  = (warps * 32 + threads - 1) / threads;
    gcn_agg_kernel<<<blocks, threads>>>(feat, nodes, neigh, out, B);
}

// round 6
// speedup vs baseline: 1.0847x; 1.0847x over previous
#include <cuda_runtime.h>
#include <cuda_bf16.h>
#include <stdint.h>

// GCN mean aggregation:
//   out[i, :] = mean over {nodes[i]} ∪ neigh_idx[i,0..31] of features[idx, :]
// features [V=100000, D=128] f32, nodes [B] int{32|64}, neigh [B,32] int{32|64}.
//
// Warp per node. KEY CHANGE vs best (47.6us): every feature load instruction
// touches exactly ONE 128B line (LDG.32: 32 lanes x 4B consecutive), so L1tex
// wavefronts issue at the 1.0 cyc/wf cross-LDG rate instead of the 2.07 cyc/wf
// within-LDG replay rate that LDG.128 (4 lines/instr) pays. 4 loads per 512B
// row; byte traffic identical.
//  - feature loads: L2::evict_last policy (keep 51MB table resident in L2)
//  - index loads / output stores: streaming (.cs)
//  - index dtype (int64 vs JAX-demoted int32) detected inline per warp by
//    probing the first 64 index words (odd words all zero <=> int64).

static constexpr int KN = 32;
static constexpr float INV_CNT = 1.0f / 33.0f;

__device__ __forceinline__ uint64_t make_keep_policy() {
    uint64_t pol;
    asm("createpolicy.fractional.L2::evict_last.b64 %0, 1.0;" : "=l"(pol));
    return pol;
}

__device__ __forceinline__ float ldg_keep1(const float* p, uint64_t pol) {
    float v;
    asm volatile("ld.global.nc.L2::cache_hint.f32 %0, [%1], %2;"
                 : "=f"(v) : "l"(p), "l"(pol));
    return v;
}

__device__ __forceinline__ void stg_stream1(float* p, float v) {
    asm volatile("st.global.cs.f32 [%0], %1;" :: "l"(p), "f"(v) : "memory");
}

__device__ __forceinline__ int2 ldg_cs32x2(const int* p) {
    int2 v;
    asm volatile("ld.global.cs.v2.s32 {%0,%1}, [%2];"
                 : "=r"(v.x), "=r"(v.y) : "l"(p));
    return v;
}

__device__ __forceinline__ long long ldg_cs64(const long long* p) {
    long long v;
    asm volatile("ld.global.cs.s64 %0, [%1];" : "=l"(v) : "l"(p));
    return v;
}

__device__ __forceinline__ int ldg_cs32(const int* p) {
    int v;
    asm volatile("ld.global.cs.s32 %0, [%1];" : "=r"(v) : "l"(p));
    return v;
}

__global__ __launch_bounds__(256) void gcn_agg_kernel(
    const float* __restrict__ feat,
    const void*  __restrict__ nodes,
    const void*  __restrict__ neigh,
    float*       __restrict__ out,
    int B)
{
    const int node = (blockIdx.x * blockDim.x + threadIdx.x) >> 5;
    const int lane = threadIdx.x & 31;
    if (node >= B) return;

    // ---- inline index-dtype detection ----
    // Probe the first 64 int32 words of neigh (valid in both dtypes: int32
    // layout has B*32 >= 64 words). Little-endian int64 values < 2^31 have
    // every odd word zero; for real int32 indices the odds of the 32 probed
    // odd-position words all being zero are ~1e-160.
    const int2 probe = ldg_cs32x2((const int*)neigh + 2 * lane);
    const bool is64 = (__ballot_sync(0xffffffffu, probe.y == 0) == 0xffffffffu);

    // ---- fetch this node's 33 indices (lane j holds neighbor j) ----
    int my_idx, self_idx;
    if (is64) {
        my_idx   = (int)ldg_cs64((const long long*)neigh + (long long)node * KN + lane);
        self_idx = (int)ldg_cs64((const long long*)nodes + node);
    } else {
        my_idx   = ldg_cs32((const int*)neigh + (long long)node * KN + lane);
        self_idx = ldg_cs32((const int*)nodes + node);
    }

    const uint64_t pol = make_keep_policy();

    // ---- gather: 4 single-line LDG.32 per row ----
    float acc0, acc1, acc2, acc3;
    {
        const float* r = feat + (long long)self_idx * 128 + lane;
        acc0 = ldg_keep1(r,      pol);
        acc1 = ldg_keep1(r + 32, pol);
        acc2 = ldg_keep1(r + 64, pol);
        acc3 = ldg_keep1(r + 96, pol);
    }
#pragma unroll
    for (int j = 0; j < KN; j++) {
        const int idx = __shfl_sync(0xffffffffu, my_idx, j);
        const float* r = feat + (long long)idx * 128 + lane;
        acc0 += ldg_keep1(r,      pol);
        acc1 += ldg_keep1(r + 32, pol);
        acc2 += ldg_keep1(r + 64, pol);
        acc3 += ldg_keep1(r + 96, pol);
    }

    float* op = out + (long long)node * 128 + lane;
    stg_stream1(op,      acc0 * INV_CNT);
    stg_stream1(op + 32, acc1 * INV_CNT);
    stg_stream1(op + 64, acc2 * INV_CNT);
    stg_stream1(op + 96, acc3 * INV_CNT);
}

extern "C" void kernel_launch(void* const* d_in, const int* in_sizes, int n_in,
                              void* d_out, int out_size) {
    const float* feat  = (const float*)d_in[0];
    const void*  nodes = d_in[1];
    const void*  neigh = d_in[2];
    float*       out   = (float*)d_out;

    const int B = in_sizes[1];  // 50000

    const int threads = 256;   // 8 warps = 8 nodes per block
    const int blocks  = (B * 32 + threads - 1) / threads;
    gcn_agg_kernel<<<blocks, threads>>>(feat, nodes, neigh, out, B);
}